// round 1
// baseline (speedup 1.0000x reference)
#include <cuda_runtime.h>
#include <math.h>

#define DET0 128
#define DET1 128
#define NVOX 128
#define VOL_ELEMS (128*128*128)
#define N_STEPS 226

__global__ void __launch_bounds__(256) drr_kernel(
    const float* __restrict__ vol,      // (4,1,128,128,128)
    const float* __restrict__ params,   // (4,6)
    float* __restrict__ out)            // (4,1,128,128)
{
    const int iv = threadIdx.x;                           // det axis 1 (fastest)
    const int iu = blockIdx.x * blockDim.y + threadIdx.y; // det axis 0
    const int b  = blockIdx.y;

    // ---- per-batch transform (uniform across block; cheap) ----
    const float* p = params + b * 6;
    float tx = p[0], ty = p[1], tz = p[2];
    float cx, sx, cy, sy, cz, sz;
    __sincosf(tx, &sx, &cx);  // fast path ok? use precise to be safe
    // use precise sin/cos (tolerance safety); overwrite:
    sx = sinf(tx); cx = cosf(tx);
    sy = sinf(ty); cy = cosf(ty);
    sz = sinf(tz); cz = cosf(tz);

    // R = Rx @ Ry @ Rz
    float R00 = cy*cz,              R01 = -cy*sz,             R02 = sy;
    float R10 = cx*sz + sx*sy*cz,   R11 = cx*cz - sx*sy*sz,   R12 = -sx*cy;
    float R20 = sx*sz - cx*sy*cz,   R21 = sx*cz + cx*sy*sz,   R22 = cx*cy;

    // Rt = R^T
    float T00 = R00, T01 = R10, T02 = R20;
    float T10 = R01, T11 = R11, T12 = R21;
    float T20 = R02, T21 = R12, T22 = R22;

    // t = -p[3:6]; t.z += ISO(1000)
    float tv0 = -p[3], tv1 = -p[4], tv2 = 1000.0f - p[5];

    // source = 64 - Rt @ t   (VOXINV = I, VOL_OFFSET = 64)
    float s0 = 64.0f - (T00*tv0 + T01*tv1 + T02*tv2);
    float s1 = 64.0f - (T10*tv0 + T11*tv1 + T12*tv2);
    float s2 = 64.0f - (T20*tv0 + T21*tv1 + T22*tv2);

    // K_INV @ pix  (K = [[1000,0,64],[0,1000,64],[0,0,1]])
    float qx = ((float)iu + 0.5f) * 0.001f - 0.064f;
    float qy = ((float)iv + 0.5f) * 0.001f - 0.064f;

    // dirs = Rt @ q
    float d0 = T00*qx + T01*qy + T02;
    float d1 = T10*qx + T11*qy + T12;
    float d2 = T20*qx + T21*qy + T22;

    // normalize (VOX = 1)
    float inv = rsqrtf(d0*d0 + d1*d1 + d2*d2);
    // match reference: d = dirs / sqrt(...)  -> use division-equivalent precision
    float nrm = sqrtf(d0*d0 + d1*d1 + d2*d2);
    d0 /= nrm; d1 /= nrm; d2 /= nrm;
    (void)inv;

    // slab intersection
    float sd0 = (fabsf(d0) < 1e-8f) ? 1e-8f : d0;
    float sd1 = (fabsf(d1) < 1e-8f) ? 1e-8f : d1;
    float sd2 = (fabsf(d2) < 1e-8f) ? 1e-8f : d2;
    float a0 = (0.0f   - s0) / sd0, b0_ = (128.0f - s0) / sd0;
    float a1 = (0.0f   - s1) / sd1, b1_ = (128.0f - s1) / sd1;
    float a2 = (0.0f   - s2) / sd2, b2_ = (128.0f - s2) / sd2;
    float tmin = fmaxf(fmaxf(fminf(a0,b0_), fminf(a1,b1_)), fminf(a2,b2_));
    tmin = fmaxf(tmin, 0.0f);
    float tmax = fminf(fminf(fmaxf(a0,b0_), fmaxf(a1,b1_)), fmaxf(a2,b2_));

    const float* __restrict__ v = vol + (size_t)b * VOL_ELEMS;

    float acc = 0.0f;
    #pragma unroll 2
    for (int k = 0; k < N_STEPS; k++) {
        float tk = tmin + ((float)k + 0.5f);
        if (tk >= tmax) break;

        float px = fmaf(tk, d0, s0);
        float py = fmaf(tk, d1, s1);
        float pz = fmaf(tk, d2, s2);

        float fx = floorf(px), fy = floorf(py), fz = floorf(pz);
        int ix = (int)fx, iy = (int)fy, iz = (int)fz;
        float rx = px - fx, ry = py - fy, rz = pz - fz;

        // per-axis weights, zeroed when the corner index is out of range
        float wx0 = ((unsigned)ix        < 128u) ? (1.0f - rx) : 0.0f;
        float wx1 = ((unsigned)(ix + 1)  < 128u) ? rx          : 0.0f;
        float wy0 = ((unsigned)iy        < 128u) ? (1.0f - ry) : 0.0f;
        float wy1 = ((unsigned)(iy + 1)  < 128u) ? ry          : 0.0f;
        float wz0 = ((unsigned)iz        < 128u) ? (1.0f - rz) : 0.0f;
        float wz1 = ((unsigned)(iz + 1)  < 128u) ? rz          : 0.0f;

        // clipped indices
        int cx0 = min(max(ix,     0), 127);
        int cx1 = min(max(ix + 1, 0), 127);
        int cy0 = min(max(iy,     0), 127);
        int cy1 = min(max(iy + 1, 0), 127);
        int cz0 = min(max(iz,     0), 127);
        int cz1 = min(max(iz + 1, 0), 127);

        int r00 = cx0 * 16384 + cy0 * 128;
        int r01 = cx0 * 16384 + cy1 * 128;
        int r10 = cx1 * 16384 + cy0 * 128;
        int r11 = cx1 * 16384 + cy1 * 128;

        float v000 = __ldg(v + r00 + cz0);
        float v001 = __ldg(v + r00 + cz1);
        float v010 = __ldg(v + r01 + cz0);
        float v011 = __ldg(v + r01 + cz1);
        float v100 = __ldg(v + r10 + cz0);
        float v101 = __ldg(v + r10 + cz1);
        float v110 = __ldg(v + r11 + cz0);
        float v111 = __ldg(v + r11 + cz1);

        float w00 = wx0 * wy0;
        float w01 = wx0 * wy1;
        float w10 = wx1 * wy0;
        float w11 = wx1 * wy1;

        float sz0v = fmaf(v000, w00, 0.0f);
        sz0v = fmaf(v010, w01, sz0v);
        sz0v = fmaf(v100, w10, sz0v);
        sz0v = fmaf(v110, w11, sz0v);
        float sz1v = fmaf(v001, w00, 0.0f);
        sz1v = fmaf(v011, w01, sz1v);
        sz1v = fmaf(v101, w10, sz1v);
        sz1v = fmaf(v111, w11, sz1v);

        acc = fmaf(sz0v, wz0, acc);
        acc = fmaf(sz1v, wz1, acc);
    }

    out[((b * DET0) + iu) * DET1 + iv] = acc * 0.1f;  // * STEP / 10
}

extern "C" void kernel_launch(void* const* d_in, const int* in_sizes, int n_in,
                              void* d_out, int out_size)
{
    const float* vol    = (const float*)d_in[0];
    const float* params = (const float*)d_in[1];
    float* out = (float*)d_out;

    dim3 block(128, 2);
    dim3 grid(DET0 / 2, 4);
    drr_kernel<<<grid, block>>>(vol, params, out);
}

// round 2
// speedup vs baseline: 4.0575x; 4.0575x over previous
#include <cuda_runtime.h>
#include <math.h>

#define DET0 128
#define DET1 128
#define VOL_ELEMS (128*128*128)
#define N_STEPS 226
#define WARPS_PER_BLOCK 8

__global__ void __launch_bounds__(WARPS_PER_BLOCK * 32) drr_kernel(
    const float* __restrict__ vol,      // (4,1,128,128,128)
    const float* __restrict__ params,   // (4,6)
    float* __restrict__ out)            // (4,1,128,128)
{
    const int lane    = threadIdx.x & 31;
    const int warp_id = threadIdx.x >> 5;
    const int ray     = blockIdx.x * WARPS_PER_BLOCK + warp_id; // 0..65535

    const int iv = ray & 127;          // det axis 1 (fastest in ray id -> block-local rays y-adjacent)
    const int iu = (ray >> 7) & 127;   // det axis 0
    const int b  = ray >> 14;          // batch

    // ---- per-ray transform setup (uniform across warp) ----
    const float* p = params + b * 6;
    float sx = sinf(p[0]), cx = cosf(p[0]);
    float sy = sinf(p[1]), cy = cosf(p[1]);
    float sz = sinf(p[2]), cz = cosf(p[2]);

    // R = Rx @ Ry @ Rz ; T = R^T
    float T00 = cy*cz,            T01 = cx*sz + sx*sy*cz,  T02 = sx*sz - cx*sy*cz;
    float T10 = -cy*sz,           T11 = cx*cz - sx*sy*sz,  T12 = sx*cz + cx*sy*sz;
    float T20 = sy,               T21 = -sx*cy,            T22 = cx*cy;

    // t = -p[3:6]; t.z += ISO(1000);  source = 64 - R^T t
    float tv0 = -p[3], tv1 = -p[4], tv2 = 1000.0f - p[5];
    float s0 = 64.0f - (T00*tv0 + T01*tv1 + T02*tv2);
    float s1 = 64.0f - (T10*tv0 + T11*tv1 + T12*tv2);
    float s2 = 64.0f - (T20*tv0 + T21*tv1 + T22*tv2);

    // K_INV @ pix
    float qx = ((float)iu + 0.5f) * 0.001f - 0.064f;
    float qy = ((float)iv + 0.5f) * 0.001f - 0.064f;

    // dirs = R^T q ; normalize
    float d0 = T00*qx + T01*qy + T02;
    float d1 = T10*qx + T11*qy + T12;
    float d2 = T20*qx + T21*qy + T22;
    float nrm = sqrtf(d0*d0 + d1*d1 + d2*d2);
    d0 /= nrm; d1 /= nrm; d2 /= nrm;

    // slab intersection
    float sd0 = (fabsf(d0) < 1e-8f) ? 1e-8f : d0;
    float sd1 = (fabsf(d1) < 1e-8f) ? 1e-8f : d1;
    float sd2 = (fabsf(d2) < 1e-8f) ? 1e-8f : d2;
    float a0 = (0.0f - s0) / sd0, b0_ = (128.0f - s0) / sd0;
    float a1 = (0.0f - s1) / sd1, b1_ = (128.0f - s1) / sd1;
    float a2 = (0.0f - s2) / sd2, b2_ = (128.0f - s2) / sd2;
    float tmin = fmaxf(fmaxf(fminf(a0,b0_), fminf(a1,b1_)), fminf(a2,b2_));
    tmin = fmaxf(tmin, 0.0f);
    float tmax = fminf(fminf(fmaxf(a0,b0_), fmaxf(a1,b1_)), fmaxf(a2,b2_));

    const float* __restrict__ v = vol + (size_t)b * VOL_ELEMS;

    float acc = 0.0f;
    // lane handles steps k = lane + 32*j
    for (int j = 0; j < (N_STEPS + 31) / 32; j++) {
        int k = j * 32 + lane;
        float tk = tmin + ((float)k + 0.5f);
        // warp-uniform early exit (tmin/tmax uniform across warp)
        if (tmin + (float)(j * 32) + 0.5f >= tmax) break;

        bool live = (k < N_STEPS) && (tk < tmax);

        float px = fmaf(tk, d0, s0);
        float py = fmaf(tk, d1, s1);
        float pz = fmaf(tk, d2, s2);

        float fx = floorf(px), fy = floorf(py), fz = floorf(pz);
        int ix = (int)fx, iy = (int)fy, iz = (int)fz;
        float rx = px - fx, ry = py - fy, rz = pz - fz;

        float wx0 = ((unsigned)ix       < 128u) ? (1.0f - rx) : 0.0f;
        float wx1 = ((unsigned)(ix + 1) < 128u) ? rx          : 0.0f;
        float wy0 = ((unsigned)iy       < 128u) ? (1.0f - ry) : 0.0f;
        float wy1 = ((unsigned)(iy + 1) < 128u) ? ry          : 0.0f;
        float wz0 = ((unsigned)iz       < 128u) ? (1.0f - rz) : 0.0f;
        float wz1 = ((unsigned)(iz + 1) < 128u) ? rz          : 0.0f;
        if (!live) { wz0 = 0.0f; wz1 = 0.0f; }

        int cx0 = min(max(ix,     0), 127);
        int cx1 = min(max(ix + 1, 0), 127);
        int cy0 = min(max(iy,     0), 127);
        int cy1 = min(max(iy + 1, 0), 127);
        int cz0 = min(max(iz,     0), 127);
        int cz1 = min(max(iz + 1, 0), 127);

        int r00 = cx0 * 16384 + cy0 * 128;
        int r01 = cx0 * 16384 + cy1 * 128;
        int r10 = cx1 * 16384 + cy0 * 128;
        int r11 = cx1 * 16384 + cy1 * 128;

        float v000 = __ldg(v + r00 + cz0);
        float v001 = __ldg(v + r00 + cz1);
        float v010 = __ldg(v + r01 + cz0);
        float v011 = __ldg(v + r01 + cz1);
        float v100 = __ldg(v + r10 + cz0);
        float v101 = __ldg(v + r10 + cz1);
        float v110 = __ldg(v + r11 + cz0);
        float v111 = __ldg(v + r11 + cz1);

        float w00 = wx0 * wy0;
        float w01 = wx0 * wy1;
        float w10 = wx1 * wy0;
        float w11 = wx1 * wy1;

        float sz0v;
        sz0v = v000 * w00;
        sz0v = fmaf(v010, w01, sz0v);
        sz0v = fmaf(v100, w10, sz0v);
        sz0v = fmaf(v110, w11, sz0v);
        float sz1v;
        sz1v = v001 * w00;
        sz1v = fmaf(v011, w01, sz1v);
        sz1v = fmaf(v101, w10, sz1v);
        sz1v = fmaf(v111, w11, sz1v);

        acc = fmaf(sz0v, wz0, acc);
        acc = fmaf(sz1v, wz1, acc);
    }

    // warp reduction
    #pragma unroll
    for (int off = 16; off > 0; off >>= 1)
        acc += __shfl_xor_sync(0xFFFFFFFFu, acc, off);

    if (lane == 0)
        out[ray] = acc * 0.1f;   // * STEP / 10
}

extern "C" void kernel_launch(void* const* d_in, const int* in_sizes, int n_in,
                              void* d_out, int out_size)
{
    const float* vol    = (const float*)d_in[0];
    const float* params = (const float*)d_in[1];
    float* out = (float*)d_out;

    int total_rays = 4 * DET0 * DET1;                 // 65536
    int blocks = total_rays / WARPS_PER_BLOCK;        // 8192
    drr_kernel<<<blocks, WARPS_PER_BLOCK * 32>>>(vol, params, out);
}

// round 3
// speedup vs baseline: 4.1844x; 1.0313x over previous
#include <cuda_runtime.h>
#include <math.h>

#define DET0 128
#define DET1 128
#define VOL_ELEMS (128*128*128)
#define N_STEPS 226
#define WARPS_PER_BLOCK 8

__global__ void __launch_bounds__(WARPS_PER_BLOCK * 32) drr_kernel(
    const float* __restrict__ vol,      // (4,1,128,128,128)
    const float* __restrict__ params,   // (4,6)
    float* __restrict__ out)            // (4,1,128,128)
{
    const int lane    = threadIdx.x & 31;
    const int warp_id = threadIdx.x >> 5;
    const int ray     = blockIdx.x * WARPS_PER_BLOCK + warp_id; // 0..65535

    const int iv = ray & 127;
    const int iu = (ray >> 7) & 127;
    const int b  = ray >> 14;

    // ---- per-ray transform setup (uniform across warp) ----
    const float* p = params + b * 6;
    float sx = sinf(p[0]), cx = cosf(p[0]);
    float sy = sinf(p[1]), cy = cosf(p[1]);
    float sz = sinf(p[2]), cz = cosf(p[2]);

    // R = Rx @ Ry @ Rz ; T = R^T
    float T00 = cy*cz,  T01 = cx*sz + sx*sy*cz,  T02 = sx*sz - cx*sy*cz;
    float T10 = -cy*sz, T11 = cx*cz - sx*sy*sz,  T12 = sx*cz + cx*sy*sz;
    float T20 = sy,     T21 = -sx*cy,            T22 = cx*cy;

    // t = -p[3:6]; t.z += ISO(1000);  source = 64 - R^T t
    float tv0 = -p[3], tv1 = -p[4], tv2 = 1000.0f - p[5];
    float s0 = 64.0f - (T00*tv0 + T01*tv1 + T02*tv2);
    float s1 = 64.0f - (T10*tv0 + T11*tv1 + T12*tv2);
    float s2 = 64.0f - (T20*tv0 + T21*tv1 + T22*tv2);

    // K_INV @ pix
    float qx = ((float)iu + 0.5f) * 0.001f - 0.064f;
    float qy = ((float)iv + 0.5f) * 0.001f - 0.064f;

    // dirs = R^T q ; normalize
    float d0 = T00*qx + T01*qy + T02;
    float d1 = T10*qx + T11*qy + T12;
    float d2 = T20*qx + T21*qy + T22;
    float nrm = sqrtf(d0*d0 + d1*d1 + d2*d2);
    d0 /= nrm; d1 /= nrm; d2 /= nrm;

    // slab intersection (full volume, matches reference)
    float sd0 = (fabsf(d0) < 1e-8f) ? 1e-8f : d0;
    float sd1 = (fabsf(d1) < 1e-8f) ? 1e-8f : d1;
    float sd2 = (fabsf(d2) < 1e-8f) ? 1e-8f : d2;
    float a0 = (0.0f - s0) / sd0, b0_ = (128.0f - s0) / sd0;
    float a1 = (0.0f - s1) / sd1, b1_ = (128.0f - s1) / sd1;
    float a2 = (0.0f - s2) / sd2, b2_ = (128.0f - s2) / sd2;
    float tmin = fmaxf(fmaxf(fminf(a0,b0_), fminf(a1,b1_)), fminf(a2,b2_));
    tmin = fmaxf(tmin, 0.0f);
    float tmax = fminf(fminf(fmaxf(a0,b0_), fmaxf(a1,b1_)), fmaxf(a2,b2_));

    // interior slab [0.5, 126.5]: inside here all 8 corners are in-range
    float e0 = (0.5f - s0) / sd0, g0 = (126.5f - s0) / sd0;
    float e1 = (0.5f - s1) / sd1, g1 = (126.5f - s1) / sd1;
    float e2 = (0.5f - s2) / sd2, g2 = (126.5f - s2) / sd2;
    float t_in  = fmaxf(fmaxf(fminf(e0,g0), fminf(e1,g1)), fminf(e2,g2));
    float t_out = fminf(fminf(fmaxf(e0,g0), fmaxf(e1,g1)), fmaxf(e2,g2));

    const float* __restrict__ v = vol + (size_t)b * VOL_ELEMS;

    float acc = 0.0f;
    for (int j = 0; j < (N_STEPS + 31) / 32; j++) {
        float tbase = tmin + (float)(j * 32);
        if (tbase + 0.5f >= tmax) break;   // warp-uniform

        int   k  = j * 32 + lane;
        float tk = tbase + (float)lane + 0.5f;

        // warp-uniform fast-path test: whole chunk strictly interior + fully live
        bool fast = (tbase + 0.5f  >= t_in) &&
                    (tbase + 31.5f <= t_out) &&
                    (tbase + 31.5f <  tmax) &&
                    (j * 32 + 31   <  N_STEPS);

        float px = fmaf(tk, d0, s0);
        float py = fmaf(tk, d1, s1);
        float pz = fmaf(tk, d2, s2);
        float fx = floorf(px), fy = floorf(py), fz = floorf(pz);
        int ix = (int)fx, iy = (int)fy, iz = (int)fz;
        float rx = px - fx, ry = py - fy, rz = pz - fz;

        if (fast) {
            // indices guaranteed in [0,126]; single base + immediate offsets
            int r = ix * 16384 + iy * 128 + iz;
            float v000 = __ldg(v + r);
            float v001 = __ldg(v + r + 1);
            float v010 = __ldg(v + r + 128);
            float v011 = __ldg(v + r + 129);
            float v100 = __ldg(v + r + 16384);
            float v101 = __ldg(v + r + 16385);
            float v110 = __ldg(v + r + 16512);
            float v111 = __ldg(v + r + 16513);

            float lz00 = fmaf(rz, v001 - v000, v000);
            float lz01 = fmaf(rz, v011 - v010, v010);
            float lz10 = fmaf(rz, v101 - v100, v100);
            float lz11 = fmaf(rz, v111 - v110, v110);
            float ly0  = fmaf(ry, lz01 - lz00, lz00);
            float ly1  = fmaf(ry, lz11 - lz10, lz10);
            acc += fmaf(rx, ly1 - ly0, ly0);
        } else {
            bool live = (k < N_STEPS) && (tk < tmax);

            float wx0 = ((unsigned)ix       < 128u) ? (1.0f - rx) : 0.0f;
            float wx1 = ((unsigned)(ix + 1) < 128u) ? rx          : 0.0f;
            float wy0 = ((unsigned)iy       < 128u) ? (1.0f - ry) : 0.0f;
            float wy1 = ((unsigned)(iy + 1) < 128u) ? ry          : 0.0f;
            float wz0 = ((unsigned)iz       < 128u) ? (1.0f - rz) : 0.0f;
            float wz1 = ((unsigned)(iz + 1) < 128u) ? rz          : 0.0f;
            if (!live) { wz0 = 0.0f; wz1 = 0.0f; }

            int cx0 = min(max(ix,     0), 127);
            int cx1 = min(max(ix + 1, 0), 127);
            int cy0 = min(max(iy,     0), 127);
            int cy1 = min(max(iy + 1, 0), 127);
            int cz0 = min(max(iz,     0), 127);
            int cz1 = min(max(iz + 1, 0), 127);

            int r00 = cx0 * 16384 + cy0 * 128;
            int r01 = cx0 * 16384 + cy1 * 128;
            int r10 = cx1 * 16384 + cy0 * 128;
            int r11 = cx1 * 16384 + cy1 * 128;

            float v000 = __ldg(v + r00 + cz0);
            float v001 = __ldg(v + r00 + cz1);
            float v010 = __ldg(v + r01 + cz0);
            float v011 = __ldg(v + r01 + cz1);
            float v100 = __ldg(v + r10 + cz0);
            float v101 = __ldg(v + r10 + cz1);
            float v110 = __ldg(v + r11 + cz0);
            float v111 = __ldg(v + r11 + cz1);

            float w00 = wx0 * wy0;
            float w01 = wx0 * wy1;
            float w10 = wx1 * wy0;
            float w11 = wx1 * wy1;

            float sz0v = v000 * w00;
            sz0v = fmaf(v010, w01, sz0v);
            sz0v = fmaf(v100, w10, sz0v);
            sz0v = fmaf(v110, w11, sz0v);
            float sz1v = v001 * w00;
            sz1v = fmaf(v011, w01, sz1v);
            sz1v = fmaf(v101, w10, sz1v);
            sz1v = fmaf(v111, w11, sz1v);

            acc = fmaf(sz0v, wz0, acc);
            acc = fmaf(sz1v, wz1, acc);
        }
    }

    // warp reduction
    #pragma unroll
    for (int off = 16; off > 0; off >>= 1)
        acc += __shfl_xor_sync(0xFFFFFFFFu, acc, off);

    if (lane == 0)
        out[ray] = acc * 0.1f;   // * STEP / 10
}

extern "C" void kernel_launch(void* const* d_in, const int* in_sizes, int n_in,
                              void* d_out, int out_size)
{
    const float* vol    = (const float*)d_in[0];
    const float* params = (const float*)d_in[1];
    float* out = (float*)d_out;

    int total_rays = 4 * DET0 * DET1;                 // 65536
    int blocks = total_rays / WARPS_PER_BLOCK;        // 8192
    drr_kernel<<<blocks, WARPS_PER_BLOCK * 32>>>(vol, params, out);
}

// round 4
// speedup vs baseline: 5.0963x; 1.2179x over previous
#include <cuda_runtime.h>
#include <math.h>

#define DET0 128
#define DET1 128
#define VOL_ELEMS (128*128*128)
#define N_STEPS 226
#define N_RAYS (4*128*128)
#define WARPS_PER_BLOCK 8

// per-ray precomputed state: [0]=(s0,s1,s2,tmin) [1]=(d0,d1,d2,tmax) [2]=(t_in,t_out,-,-)
__device__ float4 g_ray[N_RAYS * 3];

__global__ void __launch_bounds__(256) drr_setup_kernel(
    const float* __restrict__ params)   // (4,6)
{
    const int ray = blockIdx.x * 256 + threadIdx.x;
    const int iv = ray & 127;
    const int iu = (ray >> 7) & 127;
    const int b  = ray >> 14;

    const float* p = params + b * 6;
    float sx = sinf(p[0]), cx = cosf(p[0]);
    float sy = sinf(p[1]), cy = cosf(p[1]);
    float sz = sinf(p[2]), cz = cosf(p[2]);

    // R = Rx @ Ry @ Rz ; T = R^T
    float T00 = cy*cz,  T01 = cx*sz + sx*sy*cz,  T02 = sx*sz - cx*sy*cz;
    float T10 = -cy*sz, T11 = cx*cz - sx*sy*sz,  T12 = sx*cz + cx*sy*sz;
    float T20 = sy,     T21 = -sx*cy,            T22 = cx*cy;

    // t = -p[3:6]; t.z += ISO(1000);  source = 64 - R^T t
    float tv0 = -p[3], tv1 = -p[4], tv2 = 1000.0f - p[5];
    float s0 = 64.0f - (T00*tv0 + T01*tv1 + T02*tv2);
    float s1 = 64.0f - (T10*tv0 + T11*tv1 + T12*tv2);
    float s2 = 64.0f - (T20*tv0 + T21*tv1 + T22*tv2);

    // K_INV @ pix
    float qx = ((float)iu + 0.5f) * 0.001f - 0.064f;
    float qy = ((float)iv + 0.5f) * 0.001f - 0.064f;

    // dirs = R^T q ; normalize
    float d0 = T00*qx + T01*qy + T02;
    float d1 = T10*qx + T11*qy + T12;
    float d2 = T20*qx + T21*qy + T22;
    float nrm = sqrtf(d0*d0 + d1*d1 + d2*d2);
    d0 /= nrm; d1 /= nrm; d2 /= nrm;

    // slab intersection (full volume, matches reference)
    float sd0 = (fabsf(d0) < 1e-8f) ? 1e-8f : d0;
    float sd1 = (fabsf(d1) < 1e-8f) ? 1e-8f : d1;
    float sd2 = (fabsf(d2) < 1e-8f) ? 1e-8f : d2;
    float a0 = (0.0f - s0) / sd0, b0_ = (128.0f - s0) / sd0;
    float a1 = (0.0f - s1) / sd1, b1_ = (128.0f - s1) / sd1;
    float a2 = (0.0f - s2) / sd2, b2_ = (128.0f - s2) / sd2;
    float tmin = fmaxf(fmaxf(fminf(a0,b0_), fminf(a1,b1_)), fminf(a2,b2_));
    tmin = fmaxf(tmin, 0.0f);
    float tmax = fminf(fminf(fmaxf(a0,b0_), fmaxf(a1,b1_)), fmaxf(a2,b2_));

    // interior slab [0.5, 126.5]: strictly inside, all 8 corner indices in [0,126]
    float e0 = (0.5f - s0) / sd0, g0 = (126.5f - s0) / sd0;
    float e1 = (0.5f - s1) / sd1, g1 = (126.5f - s1) / sd1;
    float e2 = (0.5f - s2) / sd2, g2 = (126.5f - s2) / sd2;
    float t_in  = fmaxf(fmaxf(fminf(e0,g0), fminf(e1,g1)), fminf(e2,g2));
    float t_out = fminf(fminf(fmaxf(e0,g0), fmaxf(e1,g1)), fmaxf(e2,g2));

    g_ray[ray*3 + 0] = make_float4(s0, s1, s2, tmin);
    g_ray[ray*3 + 1] = make_float4(d0, d1, d2, tmax);
    g_ray[ray*3 + 2] = make_float4(t_in, t_out, 0.0f, 0.0f);
}

__global__ void __launch_bounds__(WARPS_PER_BLOCK * 32) drr_march_kernel(
    const float* __restrict__ vol,      // (4,1,128,128,128)
    float* __restrict__ out)            // (4,1,128,128)
{
    const int lane    = threadIdx.x & 31;
    const int warp_id = threadIdx.x >> 5;
    const int ray     = blockIdx.x * WARPS_PER_BLOCK + warp_id;
    const int b       = ray >> 14;

    const float4 A = __ldg(&g_ray[ray*3 + 0]);
    const float4 B = __ldg(&g_ray[ray*3 + 1]);
    const float4 C = __ldg(&g_ray[ray*3 + 2]);
    const float s0 = A.x, s1 = A.y, s2 = A.z, tmin = A.w;
    const float d0 = B.x, d1 = B.y, d2 = B.z, tmax = B.w;
    const float t_in = C.x, t_out = C.y;

    const float* __restrict__ v = vol + (size_t)b * VOL_ELEMS;

    const float lane_f = (float)lane + 0.5f;
    const float Lm = t_in - 0.5f;            // 0.5 safety margin absorbs rounding

    float acc = 0.0f;
    float kbase = 0.0f;                       // exact small-int float
    for (int j = 0; j < (N_STEPS + 31) / 32; j++, kbase += 32.0f) {
        // first step of this chunk: tk0 = tmin + (kbase + 0.5)
        float tk0 = tmin + (kbase + 0.5f);
        if (tk0 >= tmax) break;               // warp-uniform

        float tk = tmin + (kbase + lane_f);   // exact reference rounding
        float u  = tmin + (kbase + 31.5f);    // last step's t

        bool fast = (tk0 >= Lm + 0.5f - 0.5f) &&   // tk0 >= t_in - margin handled below
                    (tk0 >= t_in) &&
                    (u <= t_out) &&
                    (u < tmax) &&
                    (j < 7);                   // 32*6+31 = 223 < 226

        float px = fmaf(tk, d0, s0);
        float py = fmaf(tk, d1, s1);
        float pz = fmaf(tk, d2, s2);
        float fx = floorf(px), fy = floorf(py), fz = floorf(pz);
        float rx = px - fx, ry = py - fy, rz = pz - fz;

        if (fast) {
            // exact integer-valued float combine, single CVT
            float W = fmaf(fx, 16384.0f, fmaf(fy, 128.0f, fz));
            int r = (int)W;
            float v000 = __ldg(v + r);
            float v001 = __ldg(v + r + 1);
            float v010 = __ldg(v + r + 128);
            float v011 = __ldg(v + r + 129);
            float v100 = __ldg(v + r + 16384);
            float v101 = __ldg(v + r + 16385);
            float v110 = __ldg(v + r + 16512);
            float v111 = __ldg(v + r + 16513);

            float lz00 = fmaf(rz, v001 - v000, v000);
            float lz01 = fmaf(rz, v011 - v010, v010);
            float lz10 = fmaf(rz, v101 - v100, v100);
            float lz11 = fmaf(rz, v111 - v110, v110);
            float ly0  = fmaf(ry, lz01 - lz00, lz00);
            float ly1  = fmaf(ry, lz11 - lz10, lz10);
            acc += fmaf(rx, ly1 - ly0, ly0);
        } else {
            int ix = (int)fx, iy = (int)fy, iz = (int)fz;
            int k = (int)kbase + lane;
            bool live = (k < N_STEPS) && (tk < tmax);

            float wx0 = ((unsigned)ix       < 128u) ? (1.0f - rx) : 0.0f;
            float wx1 = ((unsigned)(ix + 1) < 128u) ? rx          : 0.0f;
            float wy0 = ((unsigned)iy       < 128u) ? (1.0f - ry) : 0.0f;
            float wy1 = ((unsigned)(iy + 1) < 128u) ? ry          : 0.0f;
            float wz0 = ((unsigned)iz       < 128u) ? (1.0f - rz) : 0.0f;
            float wz1 = ((unsigned)(iz + 1) < 128u) ? rz          : 0.0f;
            if (!live) { wz0 = 0.0f; wz1 = 0.0f; }

            int cx0 = min(max(ix,     0), 127);
            int cx1 = min(max(ix + 1, 0), 127);
            int cy0 = min(max(iy,     0), 127);
            int cy1 = min(max(iy + 1, 0), 127);
            int cz0 = min(max(iz,     0), 127);
            int cz1 = min(max(iz + 1, 0), 127);

            int r00 = cx0 * 16384 + cy0 * 128;
            int r01 = cx0 * 16384 + cy1 * 128;
            int r10 = cx1 * 16384 + cy0 * 128;
            int r11 = cx1 * 16384 + cy1 * 128;

            float v000 = __ldg(v + r00 + cz0);
            float v001 = __ldg(v + r00 + cz1);
            float v010 = __ldg(v + r01 + cz0);
            float v011 = __ldg(v + r01 + cz1);
            float v100 = __ldg(v + r10 + cz0);
            float v101 = __ldg(v + r10 + cz1);
            float v110 = __ldg(v + r11 + cz0);
            float v111 = __ldg(v + r11 + cz1);

            float w00 = wx0 * wy0;
            float w01 = wx0 * wy1;
            float w10 = wx1 * wy0;
            float w11 = wx1 * wy1;

            float sz0v = v000 * w00;
            sz0v = fmaf(v010, w01, sz0v);
            sz0v = fmaf(v100, w10, sz0v);
            sz0v = fmaf(v110, w11, sz0v);
            float sz1v = v001 * w00;
            sz1v = fmaf(v011, w01, sz1v);
            sz1v = fmaf(v101, w10, sz1v);
            sz1v = fmaf(v111, w11, sz1v);

            acc = fmaf(sz0v, wz0, acc);
            acc = fmaf(sz1v, wz1, acc);
        }
    }

    // warp reduction
    #pragma unroll
    for (int off = 16; off > 0; off >>= 1)
        acc += __shfl_xor_sync(0xFFFFFFFFu, acc, off);

    if (lane == 0)
        out[ray] = acc * 0.1f;   // * STEP / 10
}

extern "C" void kernel_launch(void* const* d_in, const int* in_sizes, int n_in,
                              void* d_out, int out_size)
{
    const float* vol    = (const float*)d_in[0];
    const float* params = (const float*)d_in[1];
    float* out = (float*)d_out;

    drr_setup_kernel<<<N_RAYS / 256, 256>>>(params);
    drr_march_kernel<<<N_RAYS / WARPS_PER_BLOCK, WARPS_PER_BLOCK * 32>>>(vol, out);
}